// round 13
// baseline (speedup 1.0000x reference)
#include <cuda_runtime.h>
#include <math.h>

// Fused: out = -mean_b log(y[b, argmax(target_b)] + 1e-8)
//            + sum_{b,c} w(popc(t_b^c)) * y[b,c] / (B*N),  w(0)=0, w(p)=6^p.
// N = 1024 (10 bits). Weighted sum factored: 6^popc(t^c) =
// 6^popc(tb^cb) * 6^popc(tl^j) -> 1 LDS + 4 FMA per float4 group; c==t
// exception handled by subtracting y[t] once.
// Work distribution: dynamic row dispenser (global atomic counter, grabbed
// one row ahead) -> immune to between-SM L2-die speed variance.

#define NCLS   1024
#define SMS    152
#define CPS    3
#define BLOCKS (SMS * CPS)
#define TPB    256
#define WPB    (TPB / 32)

__device__ double   g_ce = 0.0;
__device__ double   g_pt = 0.0;
__device__ unsigned g_count = 0;
__device__ unsigned g_next  = 0;     // row dispenser

__global__ __launch_bounds__(TPB, CPS)
void ce_pt_kernel(const float* __restrict__ y, const float* __restrict__ tgt,
                  float* __restrict__ out, int B) {
    __shared__ float  wtab[16];      // wtab[k] = 6^k
    __shared__ double s_ce[WPB], s_pt[WPB];

    const int tid  = threadIdx.x;
    const int lane = tid & 31;
    const int wid  = tid >> 5;

    if (tid < 16) {
        float w = 1.0f;
        for (int i = 0; i < tid && i < 9; i++) w *= 6.0f;   // exact: 6^8 < 2^24
        wtab[tid] = w;
    }
    __syncthreads();

    float  acc_pt = 0.0f;
    double acc_ce = 0.0;

    // ---- prologue: grab first row ----
    int r = 0;
    if (lane == 0) r = (int)atomicAdd(&g_next, 1u);
    r = __shfl_sync(0xFFFFFFFFu, r, 0);

    while (r < B) {
        const float4* trow = (const float4*)(tgt + (size_t)r * NCLS) + lane;
        const float4* yrow = (const float4*)(y   + (size_t)r * NCLS) + lane;

        // ---- batched preload of both rows: 16 LDG.128 in flight ----
        float4 tv[8], yv[8];
        #pragma unroll
        for (int it = 0; it < 8; it++) {
            tv[it] = __ldcs(trow + it * 32);
            yv[it] = __ldcs(yrow + it * 32);
        }

        // ---- grab next row early (ATOMG latency hides under scan+reduce) ----
        int rn = 0;
        if (lane == 0) rn = (int)atomicAdd(&g_next, 1u);

        // ---- argmax via packed u64 key (fbits<<32)|(N-1-idx) ----
        // positive uniforms -> IEEE bits monotonic; complemented idx = first-max ties.
        unsigned long long bk = 0ull;
        #pragma unroll
        for (int it = 0; it < 8; it++) {
            int c = (it * 32 + lane) * 4;
            unsigned long long k;
            k = ((unsigned long long)__float_as_uint(tv[it].x) << 32) | (unsigned)(NCLS - 1 - c);
            if (k > bk) bk = k;
            k = ((unsigned long long)__float_as_uint(tv[it].y) << 32) | (unsigned)(NCLS - 2 - c);
            if (k > bk) bk = k;
            k = ((unsigned long long)__float_as_uint(tv[it].z) << 32) | (unsigned)(NCLS - 3 - c);
            if (k > bk) bk = k;
            k = ((unsigned long long)__float_as_uint(tv[it].w) << 32) | (unsigned)(NCLS - 4 - c);
            if (k > bk) bk = k;
        }
        #pragma unroll
        for (int off = 16; off; off >>= 1) {
            unsigned long long ok = __shfl_xor_sync(0xFFFFFFFFu, bk, off);
            if (ok > bk) bk = ok;
        }
        const int t  = NCLS - 1 - (int)(bk & 0xFFFFFFFFu);   // uniform in warp
        const int tb = t >> 2;
        const int tl = t & 3;

        // ---- factored weighted sum: 1 LDS + 4 FMA per float4 group ----
        float q0 = 0.0f, q1 = 0.0f, q2 = 0.0f, q3 = 0.0f;
        float4 c4 = make_float4(0.f, 0.f, 0.f, 0.f);   // float4 containing y[t]
        #pragma unroll
        for (int it = 0; it < 8; it++) {
            const int cb = it * 32 + lane;
            const int pb = __popc(tb ^ cb);
            const float base = wtab[pb];
            const float4 v = yv[it];
            q0 = fmaf(base, v.x, q0);
            q1 = fmaf(base, v.y, q1);
            q2 = fmaf(base, v.z, q2);
            q3 = fmaf(base, v.w, q3);
            if (pb == 0) c4 = v;                        // predicated SELs
        }

        // row-final: low-bit factors {1,6,6,36} by class (tl warp-uniform)
        const float qA = (tl == 0) ? q0 : (tl == 1) ? q1 : (tl == 2) ? q2 : q3;   // tl^j==0
        const int m1 = tl ^ 1, m2 = tl ^ 2, m3 = tl ^ 3;
        const float qB = (m1 == 0) ? q0 : (m1 == 1) ? q1 : (m1 == 2) ? q2 : q3;   // ==1
        const float qC = (m2 == 0) ? q0 : (m2 == 1) ? q1 : (m2 == 2) ? q2 : q3;   // ==2
        const float qD = (m3 == 0) ? q0 : (m3 == 1) ? q1 : (m3 == 2) ? q2 : q3;   // ==3
        acc_pt += fmaf(36.0f, qD, fmaf(6.0f, qB + qC, qA));

        // ---- CE + c==t correction (owning lane holds c4) ----
        if (lane == ((t >> 2) & 31)) {
            const float yt = (tl == 0) ? c4.x : (tl == 1) ? c4.y : (tl == 2) ? c4.z : c4.w;
            acc_pt -= yt;                               // remove the +1*y[t] term
            acc_ce += (double)logf(yt + 1e-8f);
        }

        // ---- advance to the pre-grabbed row ----
        r = __shfl_sync(0xFFFFFFFFu, rn, 0);
    }

    // ---- warp reduce (once) ----
    double dpt = (double)acc_pt;
    #pragma unroll
    for (int off = 16; off; off >>= 1) {
        dpt    += __shfl_xor_sync(0xFFFFFFFFu, dpt,    off);
        acc_ce += __shfl_xor_sync(0xFFFFFFFFu, acc_ce, off);
    }
    if (lane == 0) { s_ce[wid] = acc_ce; s_pt[wid] = dpt; }
    __syncthreads();

    // ---- block reduce + fenced last-block finish ----
    if (tid == 0) {
        double bce = 0.0, bpt = 0.0;
        #pragma unroll
        for (int i = 0; i < WPB; i++) { bce += s_ce[i]; bpt += s_pt[i]; }
        atomicAdd(&g_ce, bce);
        atomicAdd(&g_pt, bpt);
        __threadfence();
        unsigned old = atomicAdd(&g_count, 1u);
        if (old == gridDim.x - 1) {
            double CE = atomicAdd(&g_ce, 0.0);   // L2 read (bypass stale L1)
            double PT = atomicAdd(&g_pt, 0.0);
            out[0] = (float)(-CE / (double)B + PT / ((double)B * (double)NCLS));
            g_ce   = 0.0;                         // reset for next graph replay
            g_pt   = 0.0;
            g_next = 0u;
            g_count = 0u;
        }
    }
}

extern "C" void kernel_launch(void* const* d_in, const int* in_sizes, int n_in,
                              void* d_out, int out_size) {
    const float* y_true = (const float*)d_in[0];
    const float* target = (const float*)d_in[1];
    const int B = in_sizes[0] / NCLS;

    ce_pt_kernel<<<BLOCKS, TPB>>>(y_true, target, (float*)d_out, B);
}

// round 14
// speedup vs baseline: 1.7393x; 1.7393x over previous
#include <cuda_runtime.h>
#include <math.h>

// Fused: out = -mean_b log(y[b, argmax(target_b)] + 1e-8)
//            + sum_{b,c} w(popc(t_b^c)) * y[b,c] / (B*N),  w(0)=0, w(p)=6^p.
// N = 1024 (10 bits). Weighted sum factored: 6^popc(t^c) =
// 6^popc(tb^cb) * 6^popc(tl^j) -> 1 LDS + 4 FMA per float4 group; the c==t
// exception handled by subtracting y[t] once.
// Work distribution: CHUNKED dynamic dispenser — one atomic per 4 rows,
// grabbed one chunk ahead, so load addresses are known ~35K cyc in advance
// and the per-row body keeps R12's batched 16-LDG schedule.

#define NCLS   1024
#define SMS    152
#define CPS    3
#define BLOCKS (SMS * CPS)
#define TPB    256
#define WPB    (TPB / 32)
#define CHUNK  4

__device__ double   g_ce = 0.0;
__device__ double   g_pt = 0.0;
__device__ unsigned g_count = 0;
__device__ unsigned g_next  = 0;     // chunk dispenser

__global__ __launch_bounds__(TPB, CPS)
void ce_pt_kernel(const float* __restrict__ y, const float* __restrict__ tgt,
                  float* __restrict__ out, int B) {
    __shared__ float  wtab[16];      // wtab[k] = 6^k
    __shared__ double s_ce[WPB], s_pt[WPB];

    const int tid  = threadIdx.x;
    const int lane = tid & 31;
    const int wid  = tid >> 5;

    if (tid < 16) {
        float w = 1.0f;
        for (int i = 0; i < tid && i < 9; i++) w *= 6.0f;   // exact: 6^8 < 2^24
        wtab[tid] = w;
    }
    __syncthreads();

    float  acc_pt = 0.0f;
    double acc_ce = 0.0;

    const int nchunks = (B + CHUNK - 1) / CHUNK;

    // ---- prologue: grab first chunk ----
    int ck = 0;
    if (lane == 0) ck = (int)atomicAdd(&g_next, 1u);
    ck = __shfl_sync(0xFFFFFFFFu, ck, 0);

    while (ck < nchunks) {
        // ---- grab NEXT chunk now: ~4 rows of latency slack before it's used ----
        int cn = 0;
        if (lane == 0) cn = (int)atomicAdd(&g_next, 1u);
        cn = __shfl_sync(0xFFFFFFFFu, cn, 0);

        const int rbase = ck * CHUNK;

        #pragma unroll 1
        for (int i = 0; i < CHUNK; i++) {
            const int r = rbase + i;
            if (r >= B) break;

            const float4* trow = (const float4*)(tgt + (size_t)r * NCLS) + lane;
            const float4* yrow = (const float4*)(y   + (size_t)r * NCLS) + lane;

            // ---- batched preload of both rows: 16 LDG.128 in flight ----
            float4 tv[8], yv[8];
            #pragma unroll
            for (int it = 0; it < 8; it++) {
                tv[it] = __ldcs(trow + it * 32);
                yv[it] = __ldcs(yrow + it * 32);
            }

            // ---- argmax via packed u64 key (fbits<<32)|(N-1-idx) ----
            // positive uniforms -> IEEE bits monotonic; complemented idx = first-max ties.
            unsigned long long bk = 0ull;
            #pragma unroll
            for (int it = 0; it < 8; it++) {
                int c = (it * 32 + lane) * 4;
                unsigned long long k;
                k = ((unsigned long long)__float_as_uint(tv[it].x) << 32) | (unsigned)(NCLS - 1 - c);
                if (k > bk) bk = k;
                k = ((unsigned long long)__float_as_uint(tv[it].y) << 32) | (unsigned)(NCLS - 2 - c);
                if (k > bk) bk = k;
                k = ((unsigned long long)__float_as_uint(tv[it].z) << 32) | (unsigned)(NCLS - 3 - c);
                if (k > bk) bk = k;
                k = ((unsigned long long)__float_as_uint(tv[it].w) << 32) | (unsigned)(NCLS - 4 - c);
                if (k > bk) bk = k;
            }
            #pragma unroll
            for (int off = 16; off; off >>= 1) {
                unsigned long long ok = __shfl_xor_sync(0xFFFFFFFFu, bk, off);
                if (ok > bk) bk = ok;
            }
            const int t  = NCLS - 1 - (int)(bk & 0xFFFFFFFFu);   // uniform in warp
            const int tb = t >> 2;
            const int tl = t & 3;

            // ---- factored weighted sum: 1 LDS + 4 FMA per float4 group ----
            float q0 = 0.0f, q1 = 0.0f, q2 = 0.0f, q3 = 0.0f;
            float4 c4 = make_float4(0.f, 0.f, 0.f, 0.f);   // float4 containing y[t]
            #pragma unroll
            for (int it = 0; it < 8; it++) {
                const int cb = it * 32 + lane;
                const int pb = __popc(tb ^ cb);
                const float base = wtab[pb];
                const float4 v = yv[it];
                q0 = fmaf(base, v.x, q0);
                q1 = fmaf(base, v.y, q1);
                q2 = fmaf(base, v.z, q2);
                q3 = fmaf(base, v.w, q3);
                if (pb == 0) c4 = v;                        // predicated SELs
            }

            // row-final: low-bit factors {1,6,6,36} by class (tl warp-uniform)
            const float qA = (tl == 0) ? q0 : (tl == 1) ? q1 : (tl == 2) ? q2 : q3;
            const int m1 = tl ^ 1, m2 = tl ^ 2, m3 = tl ^ 3;
            const float qB = (m1 == 0) ? q0 : (m1 == 1) ? q1 : (m1 == 2) ? q2 : q3;
            const float qC = (m2 == 0) ? q0 : (m2 == 1) ? q1 : (m2 == 2) ? q2 : q3;
            const float qD = (m3 == 0) ? q0 : (m3 == 1) ? q1 : (m3 == 2) ? q2 : q3;
            acc_pt += fmaf(36.0f, qD, fmaf(6.0f, qB + qC, qA));

            // ---- CE + c==t correction (owning lane holds c4) ----
            if (lane == ((t >> 2) & 31)) {
                const float yt = (tl == 0) ? c4.x : (tl == 1) ? c4.y : (tl == 2) ? c4.z : c4.w;
                acc_pt -= yt;                               // remove the +1*y[t] term
                acc_ce += (double)logf(yt + 1e-8f);
            }
        }

        ck = cn;   // advance to the pre-grabbed chunk
    }

    // ---- warp reduce (once) ----
    double dpt = (double)acc_pt;
    #pragma unroll
    for (int off = 16; off; off >>= 1) {
        dpt    += __shfl_xor_sync(0xFFFFFFFFu, dpt,    off);
        acc_ce += __shfl_xor_sync(0xFFFFFFFFu, acc_ce, off);
    }
    if (lane == 0) { s_ce[wid] = acc_ce; s_pt[wid] = dpt; }
    __syncthreads();

    // ---- block reduce + fenced last-block finish ----
    if (tid == 0) {
        double bce = 0.0, bpt = 0.0;
        #pragma unroll
        for (int i = 0; i < WPB; i++) { bce += s_ce[i]; bpt += s_pt[i]; }
        atomicAdd(&g_ce, bce);
        atomicAdd(&g_pt, bpt);
        __threadfence();
        unsigned old = atomicAdd(&g_count, 1u);
        if (old == gridDim.x - 1) {
            double CE = atomicAdd(&g_ce, 0.0);   // L2 read (bypass stale L1)
            double PT = atomicAdd(&g_pt, 0.0);
            out[0] = (float)(-CE / (double)B + PT / ((double)B * (double)NCLS));
            g_ce    = 0.0;                        // reset for next graph replay
            g_pt    = 0.0;
            g_next  = 0u;
            g_count = 0u;
        }
    }
}

extern "C" void kernel_launch(void* const* d_in, const int* in_sizes, int n_in,
                              void* d_out, int out_size) {
    const float* y_true = (const float*)d_in[0];
    const float* target = (const float*)d_in[1];
    const int B = in_sizes[0] / NCLS;

    ce_pt_kernel<<<BLOCKS, TPB>>>(y_true, target, (float*)d_out, B);
}